// round 5
// baseline (speedup 1.0000x reference)
#include <cuda_runtime.h>
#include <cuda_bf16.h>
#include <cstdint>

// ============================================================================
// VA_Aggregator via mma.sync bf16 HMMA (sm_103 baseline PTX; no tcgen05).
// K0: pre-convert W1/W2 -> bf16 interleaved SMEM-image in __device__ globals
// K1 (persistent): per 128-row tile: gather e_va/e_af (LDG), rep via <=4
//     distinct per-node loads broadcast from registers -> warp HMMA
//     MLP(192->64->64) -> in-register C->A repack -> dot(w3) -> scores
// K2: per-node softmax over L=50 + fp32 weighted gather of e_va (LDG.64).
// ============================================================================

constexpr int L      = 50;
constexpr int D      = 64;
constexpr int K1     = 192;
constexpr int TILE_M = 128;
constexpr int NMAX_ROWS = 8192 * 50;
constexpr int GRID1  = 296;

__device__ float g_scores[NMAX_ROWS];

// ---- SMEM layout (bytes from dynamic smem base) ----
constexpr int A_STRIDE  = 400;                 // 192*2 + 16 pad
constexpr int W1_STRIDE = 416;                 // 104 words ≡ 8 mod 32
constexpr int W2_STRIDE = 160;                 // 40 words  ≡ 8 mod 32
constexpr int W1_BYTES  = 64 * W1_STRIDE;      // 26624
constexpr int W2_BYTES  = 64 * W2_STRIDE;      // 10240
constexpr int OFF_A    = 0;                    // 128 * 400 = 51200
constexpr int OFF_W1   = 51200;
constexpr int OFF_W2   = 77824;
constexpr int OFF_B1   = 88064;
constexpr int OFF_B2   = 88320;
constexpr int OFF_W3   = 88576;
constexpr int OFF_B3   = 88832;
constexpr int OFF_IVA  = 88848;                // 128 i
constexpr int OFF_IAF  = 89360;
constexpr int OFF_NODF = 89872;                // 128 i : nodeOf[r] - baseNode
constexpr int OFF_REP  = 90384;                // 4 * 32 float2 = 1024 B
constexpr int SMEM_BYTES = 91408 + 32;

__device__ __align__(16) uint8_t g_w1img[W1_BYTES];
__device__ __align__(16) uint8_t g_w2img[W2_BYTES];

__device__ __forceinline__ uint32_t smem_u32(const void* p) {
    uint32_t a;
    asm("{ .reg .u64 t; cvta.to.shared.u64 t, %1; cvt.u32.u64 %0, t; }"
        : "=r"(a) : "l"(p));
    return a;
}

#define CVT_BF16X2(res, lo, hi) \
    asm("cvt.rn.satfinite.bf16x2.f32 %0, %1, %2;" : "=r"(res) : "f"(hi), "f"(lo))

#define LDSM_X4(r0, r1, r2, r3, addr) \
    asm volatile("ldmatrix.sync.aligned.m8n8.x4.shared.b16 {%0,%1,%2,%3}, [%4];" \
                 : "=r"(r0), "=r"(r1), "=r"(r2), "=r"(r3) : "r"(addr))

#define LDS_V2(r0, r1, addr) \
    asm volatile("ld.shared.v2.u32 {%0,%1}, [%2];" \
                 : "=r"(r0), "=r"(r1) : "r"(addr))

#define MMA_16816(c, a, b0, b1) \
    asm volatile("mma.sync.aligned.m16n8k16.row.col.f32.bf16.bf16.f32 " \
                 "{%0,%1,%2,%3}, {%4,%5,%6,%7}, {%8,%9}, {%0,%1,%2,%3};" \
                 : "+f"((c)[0]), "+f"((c)[1]), "+f"((c)[2]), "+f"((c)[3]) \
                 : "r"((a)[0]), "r"((a)[1]), "r"((a)[2]), "r"((a)[3]), \
                   "r"(b0), "r"(b1))

// Wt interleaved byte offset: B-fragment {k, k+1, k+8, k+9} contiguous as 8B.
__device__ __forceinline__ int wt_off(int n, int k, int stride) {
    const int kt = k >> 4, kk = k & 15;
    return n * stride + kt * 32 + ((kk & 7) >> 1) * 8 + ((kk >= 8) ? 4 : 0) + (kk & 1) * 2;
}

// ============================================================================
__global__ void __launch_bounds__(256)
prep_weights_kernel(const float* __restrict__ W1, const float* __restrict__ W2)
{
    const int i = blockIdx.x * 256 + threadIdx.x;
    if (i < K1 * D) {
        const int k = i >> 6, n = i & 63;
        *(__nv_bfloat16*)(g_w1img + wt_off(n, k, W1_STRIDE)) = __float2bfloat16(W1[i]);
    } else if (i < K1 * D + D * D) {
        const int j = i - K1 * D;
        const int k = j >> 6, n = j & 63;
        *(__nv_bfloat16*)(g_w2img + wt_off(n, k, W2_STRIDE)) = __float2bfloat16(W2[j]);
    }
}

// ============================================================================
__global__ void __launch_bounds__(256, 2)
mlp_score_kernel(const int* __restrict__ nodes,
                 const int* __restrict__ hva,
                 const int* __restrict__ haf,
                 const float* __restrict__ v2e,
                 const float* __restrict__ a2e,
                 const float* __restrict__ f2e,
                 const float* __restrict__ b1,
                 const float* __restrict__ b2,
                 const float* __restrict__ w3,
                 const float* __restrict__ b3,
                 int nTiles, int nNodes, int nRows)
{
    extern __shared__ char sm[];
    const uint32_t sbase = smem_u32(sm);

    const int tid  = threadIdx.x;
    const int lane = tid & 31;
    const int wid  = tid >> 5;

    float* sB1 = (float*)(sm + OFF_B1);
    float* sB2 = (float*)(sm + OFF_B2);
    float* sW3 = (float*)(sm + OFF_W3);
    float* sB3 = (float*)(sm + OFF_B3);
    int* sIVa  = (int*)(sm + OFF_IVA);
    int* sIAf  = (int*)(sm + OFF_IAF);
    int* sNodf = (int*)(sm + OFF_NODF);
    float2* sRep = (float2*)(sm + OFF_REP);     // [4][32]

    // ---- stage weights once per CTA (vector copies of pre-built images) ----
    {
        const uint4* s1 = (const uint4*)g_w1img;
        const uint4* s2 = (const uint4*)g_w2img;
        uint4* d1 = (uint4*)(sm + OFF_W1);
        uint4* d2 = (uint4*)(sm + OFF_W2);
        #pragma unroll 2
        for (int i = tid; i < W1_BYTES / 16; i += 256) d1[i] = s1[i];
        for (int i = tid; i < W2_BYTES / 16; i += 256) d2[i] = s2[i];
        if (tid < D) { sB1[tid] = b1[tid]; sB2[tid] = b2[tid]; sW3[tid] = w3[tid]; }
        if (tid == D) sB3[0] = b3[0];
    }

    const int m0 = wid * 16;
    const int g  = lane >> 2;
    const int tg = lane & 3;
    const uint32_t aBase  = sbase + OFF_A + (m0 + (lane & 15)) * A_STRIDE + (lane >> 4) * 16;
    const uint32_t w1Base = sbase + OFF_W1 + g * W1_STRIDE + tg * 8;
    const uint32_t w2Base = sbase + OFF_W2 + g * W2_STRIDE + tg * 8;

    for (int tile = blockIdx.x; tile < nTiles; tile += GRID1) {
        const int rowbase  = tile * TILE_M;
        const int baseNode = rowbase / L;

        __syncthreads();   // protect SMEM reuse across iterations
        if (tid < TILE_M) {
            int gr = rowbase + tid;
            if (gr >= nRows) gr = nRows - 1;
            sIVa[tid]  = hva[gr];
            sIAf[tid]  = haf[gr];
            sNodf[tid] = gr / L - baseNode;     // 0..3
        }
        if (wid < 4) {
            int nd = baseNode + wid;
            if (nd > nNodes - 1) nd = nNodes - 1;
            const int item = nodes[nd];
            sRep[wid * 32 + lane] =
                reinterpret_cast<const float2*>(v2e + (size_t)item * D)[lane];
        }
        __syncthreads();

        // per-lane bf16x2 rep values for the <=4 distinct nodes of this tile
        uint32_t pk0, pk1, pk2, pk3;
        {
            const float2 r0 = sRep[lane], r1 = sRep[32 + lane];
            const float2 r2 = sRep[64 + lane], r3 = sRep[96 + lane];
            CVT_BF16X2(pk0, r0.x, r0.y);
            CVT_BF16X2(pk1, r1.x, r1.y);
            CVT_BF16X2(pk2, r2.x, r2.y);
            CVT_BF16X2(pk3, r3.x, r3.y);
        }

        // ---- fill rep segment from registers (no LDG) ----
        #pragma unroll 4
        for (int i = 0; i < 16; ++i) {
            const int r = m0 + i;
            const int dn = sNodf[r];
            const uint32_t pk = (dn == 0) ? pk0 : (dn == 1) ? pk1 : (dn == 2) ? pk2 : pk3;
            asm volatile("st.shared.b32 [%0], %1;"
                         :: "r"(sbase + OFF_A + r * A_STRIDE + 128 + lane * 4),
                            "r"(pk) : "memory");
        }

        // ---- gather e_va / e_af, batched for MLP=8 ----
        #pragma unroll
        for (int b = 0; b < 4; ++b) {
            float2 v[8];
            uint32_t dsts[8];
            #pragma unroll
            for (int u = 0; u < 8; ++u) {
                const int t = wid + (b * 8 + u) * 8;     // 0..255
                const int r = t & 127, seg = t >> 7;     // seg 0: va, 1: af
                const float* src = seg ? (f2e + (size_t)sIAf[r] * D)
                                       : (a2e + (size_t)sIVa[r] * D);
                v[u] = reinterpret_cast<const float2*>(src)[lane];
                dsts[u] = sbase + OFF_A + r * A_STRIDE + seg * 256 + lane * 4;
            }
            #pragma unroll
            for (int u = 0; u < 8; ++u) {
                uint32_t pk;
                CVT_BF16X2(pk, v[u].x, v[u].y);
                asm volatile("st.shared.b32 [%0], %1;" :: "r"(dsts[u]), "r"(pk) : "memory");
            }
        }
        __syncthreads();

        // ---- layer 1: [16x192] @ [192x64] per warp ----
        float acc[8][4];
        #pragma unroll
        for (int j = 0; j < 8; ++j)
            #pragma unroll
            for (int q = 0; q < 4; ++q) acc[j][q] = 0.f;

        #pragma unroll
        for (int kt = 0; kt < 12; ++kt) {
            uint32_t a[4];
            LDSM_X4(a[0], a[1], a[2], a[3], aBase + kt * 32);
            #pragma unroll
            for (int j = 0; j < 8; ++j) {
                uint32_t b0v, b1v;
                LDS_V2(b0v, b1v, w1Base + j * 8 * W1_STRIDE + kt * 32);
                MMA_16816(acc[j], a, b0v, b1v);
            }
        }

        // ---- epilogue 1: bias + relu + repack C -> A fragments ----
        uint32_t a2[4][4];
        #pragma unroll
        for (int j = 0; j < 8; ++j) {
            const float2 bb = *(const float2*)(sB1 + j * 8 + tg * 2);
            const float h0 = fmaxf(acc[j][0] + bb.x, 0.f);
            const float h1 = fmaxf(acc[j][1] + bb.y, 0.f);
            const float h2 = fmaxf(acc[j][2] + bb.x, 0.f);
            const float h3 = fmaxf(acc[j][3] + bb.y, 0.f);
            CVT_BF16X2(a2[j >> 1][(j & 1) * 2 + 0], h0, h1);
            CVT_BF16X2(a2[j >> 1][(j & 1) * 2 + 1], h2, h3);
        }

        // ---- layer 2: [16x64] @ [64x64] per warp ----
        float acc2[8][4];
        #pragma unroll
        for (int j = 0; j < 8; ++j)
            #pragma unroll
            for (int q = 0; q < 4; ++q) acc2[j][q] = 0.f;

        #pragma unroll
        for (int kt = 0; kt < 4; ++kt) {
            #pragma unroll
            for (int j = 0; j < 8; ++j) {
                uint32_t b0v, b1v;
                LDS_V2(b0v, b1v, w2Base + j * 8 * W2_STRIDE + kt * 32);
                MMA_16816(acc2[j], a2[kt], b0v, b1v);
            }
        }

        // ---- epilogue 2: bias + relu + dot(w3), group-of-4 reduce ----
        float plo = 0.f, phi = 0.f;
        #pragma unroll
        for (int j = 0; j < 8; ++j) {
            const int col = j * 8 + tg * 2;
            const float2 bb = *(const float2*)(sB2 + col);
            const float2 ww = *(const float2*)(sW3 + col);
            const float v0 = fmaxf(acc2[j][0] + bb.x, 0.f);
            const float v1 = fmaxf(acc2[j][1] + bb.y, 0.f);
            const float v2 = fmaxf(acc2[j][2] + bb.x, 0.f);
            const float v3 = fmaxf(acc2[j][3] + bb.y, 0.f);
            plo = fmaf(v0, ww.x, fmaf(v1, ww.y, plo));
            phi = fmaf(v2, ww.x, fmaf(v3, ww.y, phi));
        }
        #pragma unroll
        for (int o = 1; o <= 2; o <<= 1) {
            plo += __shfl_xor_sync(0xffffffffu, plo, o);
            phi += __shfl_xor_sync(0xffffffffu, phi, o);
        }
        if (tg == 0) {
            const float b3v = sB3[0];
            const int gr = rowbase + m0 + g;
            if (gr < nRows)     g_scores[gr]     = plo + b3v;
            if (gr + 8 < nRows) g_scores[gr + 8] = phi + b3v;
        }
    }
}

// ============================================================================
__global__ void __launch_bounds__(256)
softmax_agg_kernel(const int* __restrict__ hva,
                   const float* __restrict__ a2e,
                   float* __restrict__ out, int nNodes)
{
    __shared__ float sAtt[8][52];
    __shared__ int   sIdx[8][52];
    const int lane = threadIdx.x & 31;
    const int wid  = threadIdx.x >> 5;
    const int n = blockIdx.x * 8 + wid;
    if (n >= nNodes) return;

    const float s1 = g_scores[n * L + lane];
    const bool has2 = lane < (L - 32);
    const float s2 = has2 ? g_scores[n * L + 32 + lane] : -1e30f;
    sIdx[wid][lane] = hva[n * L + lane];
    if (has2) sIdx[wid][32 + lane] = hva[n * L + 32 + lane];

    float m = fmaxf(s1, s2);
    #pragma unroll
    for (int o = 16; o > 0; o >>= 1)
        m = fmaxf(m, __shfl_xor_sync(0xffffffffu, m, o));
    const float e1 = __expf(s1 - m);
    const float e2 = has2 ? __expf(s2 - m) : 0.f;
    float ss = e1 + e2;
    #pragma unroll
    for (int o = 16; o > 0; o >>= 1)
        ss += __shfl_xor_sync(0xffffffffu, ss, o);
    const float inv = 1.f / ss;
    sAtt[wid][lane] = e1 * inv;
    if (has2) sAtt[wid][32 + lane] = e2 * inv;
    __syncwarp();

    // each lane owns columns {2*lane, 2*lane+1}: one LDG.64 per row
    float oa = 0.f, ob = 0.f;
    #pragma unroll 5
    for (int l = 0; l < L; ++l) {
        const float2 v =
            reinterpret_cast<const float2*>(a2e + (size_t)sIdx[wid][l] * D)[lane];
        const float att = sAtt[wid][l];
        oa = fmaf(att, v.x, oa);
        ob = fmaf(att, v.y, ob);
    }
    reinterpret_cast<float2*>(out + (size_t)n * D)[lane] = make_float2(oa, ob);
}

// ============================================================================
extern "C" void kernel_launch(void* const* d_in, const int* in_sizes, int n_in,
                              void* d_out, int out_size)
{
    const int*   nodes = (const int*)  d_in[0];
    const int*   hva   = (const int*)  d_in[1];
    const int*   haf   = (const int*)  d_in[2];
    const float* v2e   = (const float*)d_in[3];
    const float* a2e   = (const float*)d_in[4];
    const float* f2e   = (const float*)d_in[5];
    const float* W1    = (const float*)d_in[6];
    const float* b1    = (const float*)d_in[7];
    const float* W2    = (const float*)d_in[8];
    const float* b2    = (const float*)d_in[9];
    const float* w3    = (const float*)d_in[10];
    const float* b3    = (const float*)d_in[11];
    float* out = (float*)d_out;

    const int nNodes = in_sizes[0];
    const int nRows  = nNodes * L;
    const int nTiles = (nRows + TILE_M - 1) / TILE_M;
    const int grid2  = (nNodes + 7) / 8;

    cudaFuncSetAttribute(mlp_score_kernel,
                         cudaFuncAttributeMaxDynamicSharedMemorySize, SMEM_BYTES);

    prep_weights_kernel<<<(K1 * D + D * D + 255) / 256, 256>>>(W1, W2);
    mlp_score_kernel<<<GRID1, 256, SMEM_BYTES>>>(
        nodes, hva, haf, v2e, a2e, f2e, b1, b2, w3, b3, nTiles, nNodes, nRows);
    softmax_agg_kernel<<<grid2, 256>>>(hva, a2e, out, nNodes);
}

// round 6
// speedup vs baseline: 1.0053x; 1.0053x over previous
#include <cuda_runtime.h>
#include <cuda_bf16.h>
#include <cstdint>

// ============================================================================
// VA_Aggregator via mma.sync bf16 HMMA (sm_103 baseline PTX; no tcgen05).
// K0a/K0b/K0c: pre-convert W1/W2 -> bf16 interleaved SMEM-images, pack biases.
//   (3 prep launches also place mlp_score_kernel at global launch #4, which is
//    where the fixed ncu capture window lands.)
// K1 (persistent): per 128-row tile: gather e_va/e_af (LDG batched x16), rep
//     broadcast from registers -> warp HMMA MLP(192->64->64) -> dot(w3).
// K2: per-node softmax over L=50 + fp32 weighted gather of e_va (LDG.64).
// ============================================================================

constexpr int L      = 50;
constexpr int D      = 64;
constexpr int K1     = 192;
constexpr int TILE_M = 128;
constexpr int NMAX_ROWS = 8192 * 50;
constexpr int GRID1  = 296;

__device__ float g_scores[NMAX_ROWS];
__device__ float g_bias[256];                  // [0:64)=b1 [64:128)=b2 [128:192)=w3 [192]=b3

// ---- SMEM layout (bytes from dynamic smem base) ----
constexpr int A_STRIDE  = 400;                 // 192*2 + 16 pad (stride%128=16: ldsm conflict-free)
constexpr int W1_STRIDE = 416;                 // 104 words ≡ 8 mod 32
constexpr int W2_STRIDE = 160;                 // 40 words  ≡ 8 mod 32
constexpr int W1_BYTES  = 64 * W1_STRIDE;      // 26624
constexpr int W2_BYTES  = 64 * W2_STRIDE;      // 10240
constexpr int OFF_A    = 0;                    // 128 * 400 = 51200
constexpr int OFF_W1   = 51200;
constexpr int OFF_W2   = 77824;
constexpr int OFF_BIAS = 88064;                // 256 f (b1|b2|w3|b3)
constexpr int OFF_IVA  = 89088;                // 128 i
constexpr int OFF_IAF  = 89600;
constexpr int OFF_NODF = 90112;                // 128 i
constexpr int OFF_REP  = 90624;                // 4 * 32 float2 = 1024 B
constexpr int SMEM_BYTES = 91648 + 32;

__device__ __align__(16) uint8_t g_w1img[W1_BYTES];
__device__ __align__(16) uint8_t g_w2img[W2_BYTES];

__device__ __forceinline__ uint32_t smem_u32(const void* p) {
    uint32_t a;
    asm("{ .reg .u64 t; cvta.to.shared.u64 t, %1; cvt.u32.u64 %0, t; }"
        : "=r"(a) : "l"(p));
    return a;
}

#define CVT_BF16X2(res, lo, hi) \
    asm("cvt.rn.satfinite.bf16x2.f32 %0, %1, %2;" : "=r"(res) : "f"(hi), "f"(lo))

#define LDSM_X4(r0, r1, r2, r3, addr) \
    asm volatile("ldmatrix.sync.aligned.m8n8.x4.shared.b16 {%0,%1,%2,%3}, [%4];" \
                 : "=r"(r0), "=r"(r1), "=r"(r2), "=r"(r3) : "r"(addr))

#define LDS_V2(r0, r1, addr) \
    asm volatile("ld.shared.v2.u32 {%0,%1}, [%2];" \
                 : "=r"(r0), "=r"(r1) : "r"(addr))

#define MMA_16816(c, a, b0, b1) \
    asm volatile("mma.sync.aligned.m16n8k16.row.col.f32.bf16.bf16.f32 " \
                 "{%0,%1,%2,%3}, {%4,%5,%6,%7}, {%8,%9}, {%0,%1,%2,%3};" \
                 : "+f"((c)[0]), "+f"((c)[1]), "+f"((c)[2]), "+f"((c)[3]) \
                 : "r"((a)[0]), "r"((a)[1]), "r"((a)[2]), "r"((a)[3]), \
                   "r"(b0), "r"(b1))

// Wt interleaved byte offset: B-fragment {k, k+1, k+8, k+9} contiguous as 8B.
__device__ __forceinline__ int wt_off(int n, int k, int stride) {
    const int kt = k >> 4, kk = k & 15;
    return n * stride + kt * 32 + ((kk & 7) >> 1) * 8 + ((kk >= 8) ? 4 : 0) + (kk & 1) * 2;
}

// ============================================================================
__global__ void __launch_bounds__(256)
prep_w1_kernel(const float* __restrict__ W1)
{
    const int i = blockIdx.x * 256 + threadIdx.x;
    if (i < K1 * D) {
        const int k = i >> 6, n = i & 63;
        *(__nv_bfloat16*)(g_w1img + wt_off(n, k, W1_STRIDE)) = __float2bfloat16(W1[i]);
    }
}

__global__ void __launch_bounds__(256)
prep_w2_kernel(const float* __restrict__ W2)
{
    const int i = blockIdx.x * 256 + threadIdx.x;
    if (i < D * D) {
        const int k = i >> 6, n = i & 63;
        *(__nv_bfloat16*)(g_w2img + wt_off(n, k, W2_STRIDE)) = __float2bfloat16(W2[i]);
    }
}

__global__ void __launch_bounds__(256)
prep_bias_kernel(const float* __restrict__ b1, const float* __restrict__ b2,
                 const float* __restrict__ w3, const float* __restrict__ b3)
{
    const int i = threadIdx.x;
    float v = 0.f;
    if (i < 64)        v = b1[i];
    else if (i < 128)  v = b2[i - 64];
    else if (i < 192)  v = w3[i - 128];
    else if (i == 192) v = b3[0];
    g_bias[i] = v;
}

// ============================================================================
__global__ void __launch_bounds__(256, 2)
mlp_score_kernel(const int* __restrict__ nodes,
                 const int* __restrict__ hva,
                 const int* __restrict__ haf,
                 const float* __restrict__ v2e,
                 const float* __restrict__ a2e,
                 const float* __restrict__ f2e,
                 int nTiles, int nNodes, int nRows)
{
    extern __shared__ char sm[];
    const uint32_t sbase = smem_u32(sm);

    const int tid  = threadIdx.x;
    const int lane = tid & 31;
    const int wid  = tid >> 5;

    float* sBias = (float*)(sm + OFF_BIAS);
    float* sB1 = sBias;
    float* sB2 = sBias + 64;
    float* sW3 = sBias + 128;
    int* sIVa  = (int*)(sm + OFF_IVA);
    int* sIAf  = (int*)(sm + OFF_IAF);
    int* sNodf = (int*)(sm + OFF_NODF);
    float2* sRep = (float2*)(sm + OFF_REP);     // [4][32]

    // ---- stage weights once per CTA (vector copies of pre-built images) ----
    {
        const uint4* s1 = (const uint4*)g_w1img;
        const uint4* s2 = (const uint4*)g_w2img;
        uint4* d1 = (uint4*)(sm + OFF_W1);
        uint4* d2 = (uint4*)(sm + OFF_W2);
        #pragma unroll 2
        for (int i = tid; i < W1_BYTES / 16; i += 256) d1[i] = s1[i];
        for (int i = tid; i < W2_BYTES / 16; i += 256) d2[i] = s2[i];
        sBias[tid] = g_bias[tid];
    }

    const int m0 = wid * 16;
    const int g  = lane >> 2;
    const int tg = lane & 3;
    const uint32_t aBase  = sbase + OFF_A + (m0 + (lane & 15)) * A_STRIDE + (lane >> 4) * 16;
    const uint32_t w1Base = sbase + OFF_W1 + g * W1_STRIDE + tg * 8;
    const uint32_t w2Base = sbase + OFF_W2 + g * W2_STRIDE + tg * 8;

    for (int tile = blockIdx.x; tile < nTiles; tile += GRID1) {
        const int rowbase  = tile * TILE_M;
        const int baseNode = rowbase / L;

        __syncthreads();   // protect SMEM reuse across iterations
        if (tid < TILE_M) {
            int gr = rowbase + tid;
            if (gr >= nRows) gr = nRows - 1;
            sIVa[tid]  = hva[gr];
            sIAf[tid]  = haf[gr];
            sNodf[tid] = gr / L - baseNode;     // 0..3
        }
        if (wid < 4) {
            int nd = baseNode + wid;
            if (nd > nNodes - 1) nd = nNodes - 1;
            const int item = nodes[nd];
            sRep[wid * 32 + lane] =
                reinterpret_cast<const float2*>(v2e + (size_t)item * D)[lane];
        }
        __syncthreads();

        // per-lane bf16x2 rep values for the <=4 distinct nodes of this tile
        uint32_t pk0, pk1, pk2, pk3;
        {
            const float2 r0 = sRep[lane], r1 = sRep[32 + lane];
            const float2 r2 = sRep[64 + lane], r3 = sRep[96 + lane];
            CVT_BF16X2(pk0, r0.x, r0.y);
            CVT_BF16X2(pk1, r1.x, r1.y);
            CVT_BF16X2(pk2, r2.x, r2.y);
            CVT_BF16X2(pk3, r3.x, r3.y);
        }

        // ---- fill rep segment from registers (no LDG) ----
        #pragma unroll 4
        for (int i = 0; i < 16; ++i) {
            const int r = m0 + i;
            const int dn = sNodf[r];
            const uint32_t pk = (dn == 0) ? pk0 : (dn == 1) ? pk1 : (dn == 2) ? pk2 : pk3;
            asm volatile("st.shared.b32 [%0], %1;"
                         :: "r"(sbase + OFF_A + r * A_STRIDE + 128 + lane * 4),
                            "r"(pk) : "memory");
        }

        // ---- gather e_va / e_af: 16 LDG.64 in flight per segment ----
        #pragma unroll
        for (int seg = 0; seg < 2; ++seg) {
            const int*   sIdx = seg ? sIAf : sIVa;
            const float* tbl  = seg ? f2e  : a2e;
            float2 v[16];
            #pragma unroll
            for (int u = 0; u < 16; ++u) {
                const int r = wid + u * 8;
                v[u] = reinterpret_cast<const float2*>(tbl + (size_t)sIdx[r] * D)[lane];
            }
            #pragma unroll
            for (int u = 0; u < 16; ++u) {
                const int r = wid + u * 8;
                uint32_t pk;
                CVT_BF16X2(pk, v[u].x, v[u].y);
                asm volatile("st.shared.b32 [%0], %1;"
                             :: "r"(sbase + OFF_A + r * A_STRIDE + seg * 256 + lane * 4),
                                "r"(pk) : "memory");
            }
        }
        __syncthreads();

        // ---- layer 1: [16x192] @ [192x64] per warp ----
        float acc[8][4];
        #pragma unroll
        for (int j = 0; j < 8; ++j)
            #pragma unroll
            for (int q = 0; q < 4; ++q) acc[j][q] = 0.f;

        #pragma unroll
        for (int kt = 0; kt < 12; ++kt) {
            uint32_t a[4];
            LDSM_X4(a[0], a[1], a[2], a[3], aBase + kt * 32);
            #pragma unroll
            for (int j = 0; j < 8; ++j) {
                uint32_t b0v, b1v;
                LDS_V2(b0v, b1v, w1Base + j * 8 * W1_STRIDE + kt * 32);
                MMA_16816(acc[j], a, b0v, b1v);
            }
        }

        // ---- epilogue 1: bias + relu + repack C -> A fragments ----
        uint32_t a2[4][4];
        #pragma unroll
        for (int j = 0; j < 8; ++j) {
            const float2 bb = *(const float2*)(sB1 + j * 8 + tg * 2);
            const float h0 = fmaxf(acc[j][0] + bb.x, 0.f);
            const float h1 = fmaxf(acc[j][1] + bb.y, 0.f);
            const float h2 = fmaxf(acc[j][2] + bb.x, 0.f);
            const float h3 = fmaxf(acc[j][3] + bb.y, 0.f);
            CVT_BF16X2(a2[j >> 1][(j & 1) * 2 + 0], h0, h1);
            CVT_BF16X2(a2[j >> 1][(j & 1) * 2 + 1], h2, h3);
        }

        // ---- layer 2: [16x64] @ [64x64] per warp ----
        float acc2[8][4];
        #pragma unroll
        for (int j = 0; j < 8; ++j)
            #pragma unroll
            for (int q = 0; q < 4; ++q) acc2[j][q] = 0.f;

        #pragma unroll
        for (int kt = 0; kt < 4; ++kt) {
            #pragma unroll
            for (int j = 0; j < 8; ++j) {
                uint32_t b0v, b1v;
                LDS_V2(b0v, b1v, w2Base + j * 8 * W2_STRIDE + kt * 32);
                MMA_16816(acc2[j], a2[kt], b0v, b1v);
            }
        }

        // ---- epilogue 2: bias + relu + dot(w3), group-of-4 reduce ----
        float plo = 0.f, phi = 0.f;
        #pragma unroll
        for (int j = 0; j < 8; ++j) {
            const int col = j * 8 + tg * 2;
            const float2 bb = *(const float2*)(sB2 + col);
            const float2 ww = *(const float2*)(sW3 + col);
            const float v0 = fmaxf(acc2[j][0] + bb.x, 0.f);
            const float v1 = fmaxf(acc2[j][1] + bb.y, 0.f);
            const float v2 = fmaxf(acc2[j][2] + bb.x, 0.f);
            const float v3 = fmaxf(acc2[j][3] + bb.y, 0.f);
            plo = fmaf(v0, ww.x, fmaf(v1, ww.y, plo));
            phi = fmaf(v2, ww.x, fmaf(v3, ww.y, phi));
        }
        #pragma unroll
        for (int o = 1; o <= 2; o <<= 1) {
            plo += __shfl_xor_sync(0xffffffffu, plo, o);
            phi += __shfl_xor_sync(0xffffffffu, phi, o);
        }
        if (tg == 0) {
            const float b3v = sBias[192];
            const int gr = rowbase + m0 + g;
            if (gr < nRows)     g_scores[gr]     = plo + b3v;
            if (gr + 8 < nRows) g_scores[gr + 8] = phi + b3v;
        }
    }
}

// ============================================================================
__global__ void __launch_bounds__(256)
softmax_agg_kernel(const int* __restrict__ hva,
                   const float* __restrict__ a2e,
                   float* __restrict__ out, int nNodes)
{
    __shared__ float sAtt[8][52];
    __shared__ int   sIdx[8][52];
    const int lane = threadIdx.x & 31;
    const int wid  = threadIdx.x >> 5;
    const int n = blockIdx.x * 8 + wid;
    if (n >= nNodes) return;

    const float s1 = g_scores[n * L + lane];
    const bool has2 = lane < (L - 32);
    const float s2 = has2 ? g_scores[n * L + 32 + lane] : -1e30f;
    sIdx[wid][lane] = hva[n * L + lane];
    if (has2) sIdx[wid][32 + lane] = hva[n * L + 32 + lane];

    float m = fmaxf(s1, s2);
    #pragma unroll
    for (int o = 16; o > 0; o >>= 1)
        m = fmaxf(m, __shfl_xor_sync(0xffffffffu, m, o));
    const float e1 = __expf(s1 - m);
    const float e2 = has2 ? __expf(s2 - m) : 0.f;
    float ss = e1 + e2;
    #pragma unroll
    for (int o = 16; o > 0; o >>= 1)
        ss += __shfl_xor_sync(0xffffffffu, ss, o);
    const float inv = 1.f / ss;
    sAtt[wid][lane] = e1 * inv;
    if (has2) sAtt[wid][32 + lane] = e2 * inv;
    __syncwarp();

    // each lane owns columns {2*lane, 2*lane+1}: one LDG.64 per row
    float oa = 0.f, ob = 0.f;
    #pragma unroll 10
    for (int l = 0; l < L; ++l) {
        const float2 v =
            reinterpret_cast<const float2*>(a2e + (size_t)sIdx[wid][l] * D)[lane];
        const float att = sAtt[wid][l];
        oa = fmaf(att, v.x, oa);
        ob = fmaf(att, v.y, ob);
    }
    reinterpret_cast<float2*>(out + (size_t)n * D)[lane] = make_float2(oa, ob);
}

// ============================================================================
extern "C" void kernel_launch(void* const* d_in, const int* in_sizes, int n_in,
                              void* d_out, int out_size)
{
    const int*   nodes = (const int*)  d_in[0];
    const int*   hva   = (const int*)  d_in[1];
    const int*   haf   = (const int*)  d_in[2];
    const float* v2e   = (const float*)d_in[3];
    const float* a2e   = (const float*)d_in[4];
    const float* f2e   = (const float*)d_in[5];
    const float* W1    = (const float*)d_in[6];
    const float* b1    = (const float*)d_in[7];
    const float* W2    = (const float*)d_in[8];
    const float* b2    = (const float*)d_in[9];
    const float* w3    = (const float*)d_in[10];
    const float* b3    = (const float*)d_in[11];
    float* out = (float*)d_out;

    const int nNodes = in_sizes[0];
    const int nRows  = nNodes * L;
    const int nTiles = (nRows + TILE_M - 1) / TILE_M;
    const int grid2  = (nNodes + 7) / 8;

    cudaFuncSetAttribute(mlp_score_kernel,
                         cudaFuncAttributeMaxDynamicSharedMemorySize, SMEM_BYTES);

    // Launch sequence chosen so mlp_score_kernel is global launch #4:
    // ncu capture (observed across R1/R3/R4/R5) profiles launch #4.
    prep_w1_kernel<<<(K1 * D + 255) / 256, 256>>>(W1);
    prep_w2_kernel<<<(D * D + 255) / 256, 256>>>(W2);
    prep_bias_kernel<<<1, 256>>>(b1, b2, w3, b3);
    mlp_score_kernel<<<GRID1, 256, SMEM_BYTES>>>(
        nodes, hva, haf, v2e, a2e, f2e, nTiles, nNodes, nRows);
    softmax_agg_kernel<<<grid2, 256>>>(hva, a2e, out, nNodes);
}

// round 7
// speedup vs baseline: 1.1495x; 1.1434x over previous
#include <cuda_runtime.h>
#include <cuda_bf16.h>
#include <cstdint>

// ============================================================================
// VA_Aggregator via mma.sync bf16 HMMA (sm_103 baseline PTX; no tcgen05).
// K0a/b/c: pre-convert W1/W2 -> bf16 interleaved SMEM-images, pack biases.
//   (3 prep launches keep mlp_score_kernel at global launch #4 = ncu window.)
// K1 (persistent, WARP-AUTONOMOUS): each warp owns an independent 16-row
//     tile: self-gather (idx via shfl, rep via <=2 nodes/16 rows) -> private
//     A slab -> HMMA MLP(192->64->64) -> dot(w3) -> scores. No __syncthreads
//     in the main loop => gather latency of some warps overlaps MMA of others.
// K2: per-node softmax over L=50 + fp32 weighted gather of e_va (LDG.64).
// ============================================================================

constexpr int L      = 50;
constexpr int D      = 64;
constexpr int K1     = 192;
constexpr int NMAX_ROWS = 8192 * 50;
constexpr int GRID1  = 296;
constexpr int WARPS1 = 8;

__device__ float g_scores[NMAX_ROWS];
__device__ float g_bias[256];                  // [0:64)=b1 [64:128)=b2 [128:192)=w3 [192]=b3

// ---- SMEM layout (bytes from dynamic smem base) ----
constexpr int A_STRIDE  = 400;                 // 192*2 + 16 pad (ldsm conflict-free)
constexpr int W1_STRIDE = 416;                 // 104 words ≡ 8 mod 32
constexpr int W2_STRIDE = 160;                 // 40 words  ≡ 8 mod 32
constexpr int W1_BYTES  = 64 * W1_STRIDE;      // 26624
constexpr int W2_BYTES  = 64 * W2_STRIDE;      // 10240
constexpr int OFF_A    = 0;                    // 128 * 400 = 51200
constexpr int OFF_W1   = 51200;
constexpr int OFF_W2   = 77824;
constexpr int OFF_BIAS = 88064;                // 256 f
constexpr int SMEM_BYTES = 89088 + 32;

__device__ __align__(16) uint8_t g_w1img[W1_BYTES];
__device__ __align__(16) uint8_t g_w2img[W2_BYTES];

__device__ __forceinline__ uint32_t smem_u32(const void* p) {
    uint32_t a;
    asm("{ .reg .u64 t; cvta.to.shared.u64 t, %1; cvt.u32.u64 %0, t; }"
        : "=r"(a) : "l"(p));
    return a;
}

#define CVT_BF16X2(res, lo, hi) \
    asm("cvt.rn.satfinite.bf16x2.f32 %0, %1, %2;" : "=r"(res) : "f"(hi), "f"(lo))

#define LDSM_X4(r0, r1, r2, r3, addr) \
    asm volatile("ldmatrix.sync.aligned.m8n8.x4.shared.b16 {%0,%1,%2,%3}, [%4];" \
                 : "=r"(r0), "=r"(r1), "=r"(r2), "=r"(r3) : "r"(addr))

#define LDS_V2(r0, r1, addr) \
    asm volatile("ld.shared.v2.u32 {%0,%1}, [%2];" \
                 : "=r"(r0), "=r"(r1) : "r"(addr))

#define MMA_16816(c, a, b0, b1) \
    asm volatile("mma.sync.aligned.m16n8k16.row.col.f32.bf16.bf16.f32 " \
                 "{%0,%1,%2,%3}, {%4,%5,%6,%7}, {%8,%9}, {%0,%1,%2,%3};" \
                 : "+f"((c)[0]), "+f"((c)[1]), "+f"((c)[2]), "+f"((c)[3]) \
                 : "r"((a)[0]), "r"((a)[1]), "r"((a)[2]), "r"((a)[3]), \
                   "r"(b0), "r"(b1))

// Wt interleaved byte offset: B-fragment {k, k+1, k+8, k+9} contiguous as 8B.
__device__ __forceinline__ int wt_off(int n, int k, int stride) {
    const int kt = k >> 4, kk = k & 15;
    return n * stride + kt * 32 + ((kk & 7) >> 1) * 8 + ((kk >= 8) ? 4 : 0) + (kk & 1) * 2;
}

// ============================================================================
__global__ void __launch_bounds__(256)
prep_w1_kernel(const float* __restrict__ W1)
{
    const int i = blockIdx.x * 256 + threadIdx.x;
    if (i < K1 * D) {
        const int k = i >> 6, n = i & 63;
        *(__nv_bfloat16*)(g_w1img + wt_off(n, k, W1_STRIDE)) = __float2bfloat16(W1[i]);
    }
}

__global__ void __launch_bounds__(256)
prep_w2_kernel(const float* __restrict__ W2)
{
    const int i = blockIdx.x * 256 + threadIdx.x;
    if (i < D * D) {
        const int k = i >> 6, n = i & 63;
        *(__nv_bfloat16*)(g_w2img + wt_off(n, k, W2_STRIDE)) = __float2bfloat16(W2[i]);
    }
}

__global__ void __launch_bounds__(256)
prep_bias_kernel(const float* __restrict__ b1, const float* __restrict__ b2,
                 const float* __restrict__ w3, const float* __restrict__ b3)
{
    const int i = threadIdx.x;
    float v = 0.f;
    if (i < 64)        v = b1[i];
    else if (i < 128)  v = b2[i - 64];
    else if (i < 192)  v = w3[i - 128];
    else if (i == 192) v = b3[0];
    g_bias[i] = v;
}

// ============================================================================
__global__ void __launch_bounds__(32 * WARPS1, 2)
mlp_score_kernel(const int* __restrict__ nodes,
                 const int* __restrict__ hva,
                 const int* __restrict__ haf,
                 const float* __restrict__ v2e,
                 const float* __restrict__ a2e,
                 const float* __restrict__ f2e,
                 int nT16, int nNodes, int nRows)
{
    extern __shared__ char sm[];
    const uint32_t sbase = smem_u32(sm);

    const int tid  = threadIdx.x;
    const int lane = tid & 31;
    const int wid  = tid >> 5;

    float* sBias = (float*)(sm + OFF_BIAS);
    float* sB1 = sBias;
    float* sB2 = sBias + 64;
    float* sW3 = sBias + 128;

    // ---- stage weights once per CTA, then one block sync ----
    {
        const uint4* s1 = (const uint4*)g_w1img;
        const uint4* s2 = (const uint4*)g_w2img;
        uint4* d1 = (uint4*)(sm + OFF_W1);
        uint4* d2 = (uint4*)(sm + OFF_W2);
        #pragma unroll 2
        for (int i = tid; i < W1_BYTES / 16; i += 32 * WARPS1) d1[i] = s1[i];
        for (int i = tid; i < W2_BYTES / 16; i += 32 * WARPS1) d2[i] = s2[i];
        sBias[tid] = g_bias[tid];
    }
    __syncthreads();

    const int g  = lane >> 2;
    const int tg = lane & 3;
    const uint32_t aWarp  = sbase + OFF_A + wid * 16 * A_STRIDE;
    const uint32_t aBase  = aWarp + (lane & 15) * A_STRIDE + (lane >> 4) * 16;
    const uint32_t w1Base = sbase + OFF_W1 + g * W1_STRIDE + tg * 8;
    const uint32_t w2Base = sbase + OFF_W2 + g * W2_STRIDE + tg * 8;

    const int gwarp = blockIdx.x * WARPS1 + wid;
    const int totalWarps = GRID1 * WARPS1;
    const float b3v = sBias[192];

    for (int t16 = gwarp; t16 < nT16; t16 += totalWarps) {
        const int r0 = t16 * 16;

        // ---- own history indices: lanes 0-15 -> va, lanes 16-31 -> af ----
        int rr = r0 + (lane & 15);
        if (rr > nRows - 1) rr = nRows - 1;
        const int myIdx = (lane < 16) ? hva[rr] : haf[rr];

        // ---- rep: 16 rows span at most 2 nodes ----
        const int node0  = r0 / L;
        const int nbound = (node0 + 1) * L - r0;     // rows [0, nbound) -> node0
        int n1 = node0 + 1; if (n1 > nNodes - 1) n1 = nNodes - 1;
        const int item0 = nodes[node0];
        const int item1 = nodes[n1];
        const float2 rv0 = reinterpret_cast<const float2*>(v2e + (size_t)item0 * D)[lane];
        const float2 rv1 = reinterpret_cast<const float2*>(v2e + (size_t)item1 * D)[lane];
        uint32_t pk0, pk1;
        CVT_BF16X2(pk0, rv0.x, rv0.y);
        CVT_BF16X2(pk1, rv1.x, rv1.y);

        // ---- fill rep segment ----
        #pragma unroll 4
        for (int i = 0; i < 16; ++i) {
            const uint32_t pk = (i < nbound) ? pk0 : pk1;
            asm volatile("st.shared.b32 [%0], %1;"
                         :: "r"(aWarp + i * A_STRIDE + 128 + lane * 4),
                            "r"(pk) : "memory");
        }

        // ---- gather e_va rows (16 LDG.64 in flight) ----
        {
            float2 v[16];
            #pragma unroll
            for (int u = 0; u < 16; ++u) {
                const int idx = __shfl_sync(0xffffffffu, myIdx, u);
                v[u] = reinterpret_cast<const float2*>(a2e + (size_t)idx * D)[lane];
            }
            #pragma unroll
            for (int u = 0; u < 16; ++u) {
                uint32_t pk;
                CVT_BF16X2(pk, v[u].x, v[u].y);
                asm volatile("st.shared.b32 [%0], %1;"
                             :: "r"(aWarp + u * A_STRIDE + lane * 4), "r"(pk) : "memory");
            }
        }
        // ---- gather e_af rows ----
        {
            float2 v[16];
            #pragma unroll
            for (int u = 0; u < 16; ++u) {
                const int idx = __shfl_sync(0xffffffffu, myIdx, u + 16);
                v[u] = reinterpret_cast<const float2*>(f2e + (size_t)idx * D)[lane];
            }
            #pragma unroll
            for (int u = 0; u < 16; ++u) {
                uint32_t pk;
                CVT_BF16X2(pk, v[u].x, v[u].y);
                asm volatile("st.shared.b32 [%0], %1;"
                             :: "r"(aWarp + u * A_STRIDE + 256 + lane * 4), "r"(pk) : "memory");
            }
        }
        __syncwarp();

        // ---- layer 1: [16x192] @ [192x64] ----
        float acc[8][4];
        #pragma unroll
        for (int j = 0; j < 8; ++j)
            #pragma unroll
            for (int q = 0; q < 4; ++q) acc[j][q] = 0.f;

        #pragma unroll
        for (int kt = 0; kt < 12; ++kt) {
            uint32_t a[4];
            LDSM_X4(a[0], a[1], a[2], a[3], aBase + kt * 32);
            #pragma unroll
            for (int j = 0; j < 8; ++j) {
                uint32_t b0v, b1v;
                LDS_V2(b0v, b1v, w1Base + j * 8 * W1_STRIDE + kt * 32);
                MMA_16816(acc[j], a, b0v, b1v);
            }
        }

        // ---- epilogue 1: bias + relu + repack C -> A fragments ----
        uint32_t a2[4][4];
        #pragma unroll
        for (int j = 0; j < 8; ++j) {
            const float2 bb = *(const float2*)(sB1 + j * 8 + tg * 2);
            const float h0 = fmaxf(acc[j][0] + bb.x, 0.f);
            const float h1 = fmaxf(acc[j][1] + bb.y, 0.f);
            const float h2 = fmaxf(acc[j][2] + bb.x, 0.f);
            const float h3 = fmaxf(acc[j][3] + bb.y, 0.f);
            CVT_BF16X2(a2[j >> 1][(j & 1) * 2 + 0], h0, h1);
            CVT_BF16X2(a2[j >> 1][(j & 1) * 2 + 1], h2, h3);
        }

        // ---- layer 2: [16x64] @ [64x64] ----
        float acc2[8][4];
        #pragma unroll
        for (int j = 0; j < 8; ++j)
            #pragma unroll
            for (int q = 0; q < 4; ++q) acc2[j][q] = 0.f;

        #pragma unroll
        for (int kt = 0; kt < 4; ++kt) {
            #pragma unroll
            for (int j = 0; j < 8; ++j) {
                uint32_t b0v, b1v;
                LDS_V2(b0v, b1v, w2Base + j * 8 * W2_STRIDE + kt * 32);
                MMA_16816(acc2[j], a2[kt], b0v, b1v);
            }
        }

        // ---- epilogue 2: bias + relu + dot(w3), group-of-4 reduce ----
        float plo = 0.f, phi = 0.f;
        #pragma unroll
        for (int j = 0; j < 8; ++j) {
            const int col = j * 8 + tg * 2;
            const float2 bb = *(const float2*)(sB2 + col);
            const float2 ww = *(const float2*)(sW3 + col);
            const float v0 = fmaxf(acc2[j][0] + bb.x, 0.f);
            const float v1 = fmaxf(acc2[j][1] + bb.y, 0.f);
            const float v2 = fmaxf(acc2[j][2] + bb.x, 0.f);
            const float v3 = fmaxf(acc2[j][3] + bb.y, 0.f);
            plo = fmaf(v0, ww.x, fmaf(v1, ww.y, plo));
            phi = fmaf(v2, ww.x, fmaf(v3, ww.y, phi));
        }
        #pragma unroll
        for (int o = 1; o <= 2; o <<= 1) {
            plo += __shfl_xor_sync(0xffffffffu, plo, o);
            phi += __shfl_xor_sync(0xffffffffu, phi, o);
        }
        if (tg == 0) {
            const int gr = r0 + g;
            if (gr < nRows)     g_scores[gr]     = plo + b3v;
            if (gr + 8 < nRows) g_scores[gr + 8] = phi + b3v;
        }
        __syncwarp();   // A slab reuse in next iteration
    }
}

// ============================================================================
__global__ void __launch_bounds__(256)
softmax_agg_kernel(const int* __restrict__ hva,
                   const float* __restrict__ a2e,
                   float* __restrict__ out, int nNodes)
{
    __shared__ float sAtt[8][52];
    __shared__ int   sIdx[8][52];
    const int lane = threadIdx.x & 31;
    const int wid  = threadIdx.x >> 5;
    const int n = blockIdx.x * 8 + wid;
    if (n >= nNodes) return;

    const float s1 = g_scores[n * L + lane];
    const bool has2 = lane < (L - 32);
    const float s2 = has2 ? g_scores[n * L + 32 + lane] : -1e30f;
    sIdx[wid][lane] = hva[n * L + lane];
    if (has2) sIdx[wid][32 + lane] = hva[n * L + 32 + lane];

    float m = fmaxf(s1, s2);
    #pragma unroll
    for (int o = 16; o > 0; o >>= 1)
        m = fmaxf(m, __shfl_xor_sync(0xffffffffu, m, o));
    const float e1 = __expf(s1 - m);
    const float e2 = has2 ? __expf(s2 - m) : 0.f;
    float ss = e1 + e2;
    #pragma unroll
    for (int o = 16; o > 0; o >>= 1)
        ss += __shfl_xor_sync(0xffffffffu, ss, o);
    const float inv = 1.f / ss;
    sAtt[wid][lane] = e1 * inv;
    if (has2) sAtt[wid][32 + lane] = e2 * inv;
    __syncwarp();

    float oa = 0.f, ob = 0.f;
    #pragma unroll 10
    for (int l = 0; l < L; ++l) {
        const float2 v =
            reinterpret_cast<const float2*>(a2e + (size_t)sIdx[wid][l] * D)[lane];
        const float att = sAtt[wid][l];
        oa = fmaf(att, v.x, oa);
        ob = fmaf(att, v.y, ob);
    }
    reinterpret_cast<float2*>(out + (size_t)n * D)[lane] = make_float2(oa, ob);
}

// ============================================================================
extern "C" void kernel_launch(void* const* d_in, const int* in_sizes, int n_in,
                              void* d_out, int out_size)
{
    const int*   nodes = (const int*)  d_in[0];
    const int*   hva   = (const int*)  d_in[1];
    const int*   haf   = (const int*)  d_in[2];
    const float* v2e   = (const float*)d_in[3];
    const float* a2e   = (const float*)d_in[4];
    const float* f2e   = (const float*)d_in[5];
    const float* W1    = (const float*)d_in[6];
    const float* b1    = (const float*)d_in[7];
    const float* W2    = (const float*)d_in[8];
    const float* b2    = (const float*)d_in[9];
    const float* w3    = (const float*)d_in[10];
    const float* b3    = (const float*)d_in[11];
    float* out = (float*)d_out;

    const int nNodes = in_sizes[0];
    const int nRows  = nNodes * L;
    const int nT16   = (nRows + 15) / 16;
    const int grid2  = (nNodes + 7) / 8;

    cudaFuncSetAttribute(mlp_score_kernel,
                         cudaFuncAttributeMaxDynamicSharedMemorySize, SMEM_BYTES);

    // mlp_score_kernel stays at global launch #4 (= the ncu capture window).
    prep_w1_kernel<<<(K1 * D + 255) / 256, 256>>>(W1);
    prep_w2_kernel<<<(D * D + 255) / 256, 256>>>(W2);
    prep_bias_kernel<<<1, 256>>>(b1, b2, w3, b3);
    mlp_score_kernel<<<GRID1, 32 * WARPS1, SMEM_BYTES>>>(
        nodes, hva, haf, v2e, a2e, f2e, nT16, nNodes, nRows);
    softmax_agg_kernel<<<grid2, 256>>>(hva, a2e, out, nNodes);
}